// round 15
// baseline (speedup 1.0000x reference)
#include <cuda_runtime.h>
#include <cuda_fp16.h>
#include <cstdint>
#include <mma.h>
#include <math.h>

using namespace nvcuda;

#define HEADS   8
#define NSEQ    49
#define GRID7   7
#define DMODEL  512
#define BATCH   2048
#define MROWS   (BATCH * NSEQ)   // 100352 = 784 * 128
#define MTILES  (MROWS / 128)    // 784

// ---------------- scratch (no allocations allowed) ----------------
__device__ __half g_qh [(size_t)MROWS * DMODEL];    // half inputs (GEMM A)
__device__ __half g_kh [(size_t)MROWS * DMODEL];
__device__ __half g_vh [(size_t)MROWS * DMODEL];
__device__ __half g_qph[(size_t)MROWS * DMODEL];    // q projection (half)
__device__ __half g_kph[(size_t)MROWS * DMODEL];    // k projection (half)
__device__ __half g_voh[(size_t)MROWS * DMODEL];    // vo projection (half)
__device__ __half g_wqh[DMODEL * DMODEL];
__device__ __half g_wkh[DMODEL * DMODEL];
__device__ __half g_wvoh[DMODEL * DMODEL];
__device__ float  g_bvo[DMODEL];

// ---------------- small helpers ----------------
__device__ __forceinline__ uint32_t h2_bits(__half2 h) {
    union { __half2 h; uint32_t u; } cvt; cvt.h = h; return cvt.u;
}
__device__ __forceinline__ __half2 u2h2(uint32_t u) {
    union { uint32_t u; __half2 h; } cvt; cvt.u = u; return cvt.h;
}
__device__ __forceinline__ uint2 pack4(float x, float y, float z, float w) {
    return make_uint2(h2_bits(__floats2half2_rn(x, y)),
                      h2_bits(__floats2half2_rn(z, w)));
}
__device__ __forceinline__ float2 h2f(uint32_t u) {
    return __half22float2(u2h2(u));
}
// dot of 8 halves: half2 partial chain (4 products), then fp32 reduce
__device__ __forceinline__ float dot8h(uint4 a, uint4 b) {
    __half2 p = __hmul2(u2h2(a.x), u2h2(b.x));
    p = __hfma2(u2h2(a.y), u2h2(b.y), p);
    p = __hfma2(u2h2(a.z), u2h2(b.z), p);
    p = __hfma2(u2h2(a.w), u2h2(b.w), p);
    float2 f = __half22float2(p);
    return f.x + f.y;
}

// ---------------- cp.async helpers ----------------
__device__ __forceinline__ void cp16(void* smem, const void* gmem) {
    uint32_t s = (uint32_t)__cvta_generic_to_shared(smem);
    asm volatile("cp.async.cg.shared.global [%0], [%1], 16;\n" :: "r"(s), "l"(gmem));
}
__device__ __forceinline__ void cp_commit() {
    asm volatile("cp.async.commit_group;\n");
}
template <int N>
__device__ __forceinline__ void cp_wait() {
    asm volatile("cp.async.wait_group %0;\n" :: "n"(N));
}

// =====================================================================
// Input conversion: fp32 -> fp16 for queries/keys/values (one pass).
// =====================================================================
__global__ __launch_bounds__(512)
void conv_inputs(const float4* __restrict__ q, const float4* __restrict__ k,
                 const float4* __restrict__ v,
                 uint2* __restrict__ qh, uint2* __restrict__ kh,
                 uint2* __restrict__ vh)
{
    size_t i = (size_t)blockIdx.x * 512 + threadIdx.x;
    float4 a = q[i];
    float4 b = k[i];
    float4 c = v[i];
    qh[i] = pack4(a.x, a.y, a.z, a.w);
    kh[i] = pack4(b.x, b.y, b.z, b.w);
    vh[i] = pack4(c.x, c.y, c.z, c.w);
}

// =====================================================================
// Weight prep: Wvo = per-head Wo_h @ Wv_h (half), bvo; Wq/Wk -> half.
// =====================================================================
__global__ __launch_bounds__(256)
void prep_weights(const float* __restrict__ Wo, const float* __restrict__ Wv,
                  const float* __restrict__ bv,
                  const float4* __restrict__ Wq, const float4* __restrict__ Wk,
                  __half* __restrict__ wvoh, float* __restrict__ bvo,
                  uint2* __restrict__ wqh, uint2* __restrict__ wkh)
{
    int idx = blockIdx.x * 256 + threadIdx.x;   // 65536 = 512*512/4
    int n = idx >> 7, i4 = idx & 127;
    int h = n >> 6, o = n & 63;
    const float* worow = Wo + (size_t)o * DMODEL + h * 64;
    const float4* wv4  = reinterpret_cast<const float4*>(Wv);
    float4 acc = make_float4(0.f, 0.f, 0.f, 0.f);
#pragma unroll 8
    for (int t = 0; t < 64; t++) {
        float w = worow[t];
        float4 x = wv4[(size_t)(h * 64 + t) * 128 + i4];
        acc.x += w * x.x; acc.y += w * x.y; acc.z += w * x.z; acc.w += w * x.w;
    }
    reinterpret_cast<uint2*>(wvoh)[(size_t)n * 128 + i4] =
        pack4(acc.x, acc.y, acc.z, acc.w);

    float4 a = Wq[idx];
    float4 b = Wk[idx];
    wqh[idx] = pack4(a.x, a.y, a.z, a.w);
    wkh[idx] = pack4(b.x, b.y, b.z, b.w);

    if (idx < DMODEL) {
        int h2 = idx >> 6, o2 = idx & 63;
        float s = 0.f;
        for (int t = 0; t < 64; t++)
            s += Wo[(size_t)o2 * DMODEL + h2 * 64 + t] * bv[h2 * 64 + t];
        bvo[idx] = s;
    }
}

// =====================================================================
// fp16 WMMA GEMM, 2-stage cp.async pipeline, BK=64, one barrier/chunk,
// BM=128, BN=256, 256 threads (8 warps 2m x 4n -> 64x64 warp tiles).
// 32 LDSM : 64 mma per chunk (0.5 ratio) AND 2 CTAs/SM (smem 110.6KB)
// -> 16 warps/SM. Pipeline: wait<0> -> sync -> issue(kc+1) -> compute.
//   C[M,512] = A[M,512] @ W[512,512]^T + bias   (all outputs fp16)
// =====================================================================
#define BKH     64
#define BKP     72
#define STAGES  2
#define A_STAGE (128 * BKP * 2)                     // 18432
#define W_STAGE (256 * BKP * 2)                     // 36864
#define GEMM_SMEM (STAGES * (A_STAGE + W_STAGE))    // 110592

__global__ __launch_bounds__(256, 2)
void qkv_gemm_h(const __half* __restrict__ Aq, const __half* __restrict__ Ak,
                const __half* __restrict__ Av,
                const __half* __restrict__ Wqh, const __half* __restrict__ Wkh,
                const __half* __restrict__ Wvoh,
                const float* __restrict__ bq, const float* __restrict__ bk,
                const float* __restrict__ bvo,
                __half* __restrict__ Cq, __half* __restrict__ Ck,
                __half* __restrict__ Cv)
{
    extern __shared__ __align__(16) unsigned char dynsmem[];
    __half (*As)[128][BKP] =
        reinterpret_cast<__half (*)[128][BKP]>(dynsmem);
    __half (*Ws)[256][BKP] =
        reinterpret_cast<__half (*)[256][BKP]>(dynsmem + STAGES * A_STAGE);
    float (*stage)[16][20] = reinterpret_cast<float (*)[16][20]>(dynsmem);

    const int z = blockIdx.z;
    const __half* A    = (z == 0) ? Aq  : (z == 1) ? Ak  : Av;
    const __half* W    = (z == 0) ? Wqh : (z == 1) ? Wkh : Wvoh;
    const float*  bias = (z == 0) ? bq  : (z == 1) ? bk  : bvo;
    __half*       C    = (z == 0) ? Cq  : (z == 1) ? Ck  : Cv;

    const int tid  = threadIdx.x;
    const int warp = tid >> 5;
    const int lane = tid & 31;
    const int wm   = warp >> 2;          // 0..1 -> 64 rows each
    const int wn   = warp & 3;           // 0..3 -> 64 cols each
    const int m0   = blockIdx.y * 128;
    const int n0   = blockIdx.x * 256;

    wmma::fragment<wmma::accumulator, 16, 16, 16, float> acc[4][4];
#pragma unroll
    for (int mf = 0; mf < 4; mf++)
#pragma unroll
        for (int nf = 0; nf < 4; nf++)
            wmma::fill_fragment(acc[mf][nf], 0.0f);

    // per stage: A = 1024 cp16 (4/thread), W = 2048 cp16 (8/thread)
    auto issue_stage = [&](int kc, int s) {
#pragma unroll
        for (int r = 0; r < 4; r++) {
            int idx = tid + r * 256;
            int row = idx >> 3, lc = idx & 7;
            cp16(&As[s][row][lc * 8],
                 A + (size_t)(m0 + row) * DMODEL + kc * BKH + lc * 8);
        }
#pragma unroll
        for (int r = 0; r < 8; r++) {
            int idx = tid + r * 256;
            int row = idx >> 3, lc = idx & 7;
            cp16(&Ws[s][row][lc * 8],
                 W + (size_t)(n0 + row) * DMODEL + kc * BKH + lc * 8);
        }
        cp_commit();
    };

    const int nk = DMODEL / BKH;   // 8
    issue_stage(0, 0);

    for (int kc = 0; kc < nk; kc++) {
        cp_wait<0>();          // only group kc is outstanding here
        __syncthreads();       // group kc visible to all; buffer (kc+1)&1 free
        if (kc + 1 < nk) issue_stage(kc + 1, (kc + 1) & 1);

        const int buf = kc & 1;
#pragma unroll
        for (int ks = 0; ks < BKH; ks += 16) {
            wmma::fragment<wmma::matrix_b, 16, 16, 16, __half, wmma::col_major> bf[4];
#pragma unroll
            for (int nf = 0; nf < 4; nf++)
                wmma::load_matrix_sync(bf[nf], &Ws[buf][wn * 64 + nf * 16][ks], BKP);
#pragma unroll
            for (int mf = 0; mf < 4; mf++) {
                wmma::fragment<wmma::matrix_a, 16, 16, 16, __half, wmma::row_major> af;
                wmma::load_matrix_sync(af, &As[buf][wm * 64 + mf * 16][ks], BKP);
#pragma unroll
                for (int nf = 0; nf < 4; nf++)
                    wmma::mma_sync(acc[mf][nf], af, bf[nf], acc[mf][nf]);
            }
        }
    }
    __syncthreads();   // all warps done with final tiles before stage alias reuse

    // ---- epilogue: stage fragments, add bias, pack fp16, store 16B ----
#pragma unroll
    for (int mf = 0; mf < 4; mf++)
#pragma unroll
        for (int nf = 0; nf < 4; nf++) {
            wmma::store_matrix_sync(&stage[warp][0][0], acc[mf][nf], 20,
                                    wmma::mem_row_major);
            __syncwarp();
            int r  = lane >> 1;
            int c  = (lane & 1) * 8;
            int gm = m0 + wm * 64 + mf * 16 + r;
            int gn = n0 + wn * 64 + nf * 16 + c;
            float4 v0 = *reinterpret_cast<float4*>(&stage[warp][r][c]);
            float4 v1 = *reinterpret_cast<float4*>(&stage[warp][r][c + 4]);
            float4 b0 = *reinterpret_cast<const float4*>(&bias[gn]);
            float4 b1 = *reinterpret_cast<const float4*>(&bias[gn + 4]);
            uint2 p0 = pack4(v0.x + b0.x, v0.y + b0.y, v0.z + b0.z, v0.w + b0.w);
            uint2 p1 = pack4(v1.x + b1.x, v1.y + b1.y, v1.z + b1.z, v1.w + b1.w);
            *reinterpret_cast<uint4*>(&C[(size_t)gm * DMODEL + gn]) =
                make_uint4(p0.x, p0.y, p1.x, p1.y);
            __syncwarp();
        }
}

// =====================================================================
// Sparse dilated attention. One block per batch, 256 threads, 8 heads
// sequential; head tiles DOUBLE-BUFFERED via cp.async (load h+1 while
// computing h) -> 2 barriers/head, no exposed load latency.
// HFMA2 partial dots; zinv via 8-lane shuffles (full-warp uniform);
// vo column sums on threads 192..199; output partials in registers.
// =====================================================================
__global__ __launch_bounds__(256)
void dilate_attn(const __half* __restrict__ qh, const __half* __restrict__ kh,
                 const __half* __restrict__ voh, const float* __restrict__ bo,
                 float* __restrict__ out)
{
    __shared__ uint4 tq[2][NSEQ][9];   // 64 halves/row (8 used; +1 pad)
    __shared__ uint4 tk[2][NSEQ][9];
    __shared__ uint4 tvo[2][NSEQ][9];
    __shared__ float wgt[NSEQ][8];
    __shared__ float zinv[NSEQ];
    __shared__ float vsumf[64];
    __shared__ int   nbr[NSEQ][8];
    __shared__ int   cnt[NSEQ];

    const int b   = blockIdx.x;
    const int tid = threadIdx.x;
    const size_t bbase = (size_t)b * NSEQ * DMODEL;   // element units
    const uint4* q4 = reinterpret_cast<const uint4*>(qh);
    const uint4* k4 = reinterpret_cast<const uint4*>(kh);
    const uint4* v4 = reinterpret_cast<const uint4*>(voh);

    if (tid < NSEQ) {
        int r = tid / GRID7, c = tid % GRID7;
        int n = 0;
#pragma unroll
        for (int dr = -1; dr <= 1; dr++)
#pragma unroll
            for (int dc = -1; dc <= 1; dc++) {
                if (dr == 0 && dc == 0) continue;
                int rr = r + dr, cc = c + dc;
                if (rr >= 0 && rr < GRID7 && cc >= 0 && cc < GRID7)
                    nbr[tid][n++] = rr * GRID7 + cc;
            }
        cnt[tid] = n;
        for (int l = n; l < 8; l++) nbr[tid][l] = 0;
    }

    auto issue_head = [&](int h, int buf) {
        size_t base8 = (bbase + h * 64) / 8;   // uint4 units
#pragma unroll
        for (int s2 = 0; s2 < 2; s2++) {
            int e = tid + s2 * 256;
            if (e < NSEQ * 8) {
                int n = e >> 3, d8 = e & 7;
                size_t g = base8 + (size_t)n * 64 + d8;
                cp16(&tq[buf][n][d8],  q4 + g);
                cp16(&tk[buf][n][d8],  k4 + g);
                cp16(&tvo[buf][n][d8], v4 + g);
            }
        }
        cp_commit();
    };

    // register output accumulators: slot = tid + s2*256 -> (i = slot/8, d8 = slot%8)
    float racc[2][8];
#pragma unroll
    for (int s2 = 0; s2 < 2; s2++)
#pragma unroll
        for (int e = 0; e < 8; e++) racc[s2][e] = 0.f;

    issue_head(0, 0);

    for (int h = 0; h < HEADS; h++) {
        const int buf = h & 1;
        cp_wait<0>();       // only group h outstanding here
        __syncthreads();    // tiles h visible; output(h-1) done (wgt/buf reuse safe)
        if (h + 1 < HEADS) issue_head(h + 1, buf ^ 1);

        // ---- sparse QK dots + per-row zinv (uniform full-warp shuffles) ----
#pragma unroll
        for (int s2 = 0; s2 < 2; s2++) {
            int slot = tid + s2 * 256;
            bool valid = slot < NSEQ * 8;
            int i = valid ? (slot >> 3) : 0;
            int l = slot & 7;
            float w = 0.f;
            if (valid && l < cnt[i]) {
                int j = nbr[i][l];
                float dot = 0.f;
#pragma unroll
                for (int d8 = 0; d8 < 8; d8++)
                    dot += dot8h(tq[buf][i][d8], tk[buf][j][d8]);
                w = __expf(dot * 0.125f) - 1.f;
            }
            if (valid) wgt[i][l] = w;
            float zs = w;   // all 32 lanes participate; invalid lanes carry 0
            zs += __shfl_down_sync(0xFFFFFFFFu, zs, 4, 8);
            zs += __shfl_down_sync(0xFFFFFFFFu, zs, 2, 8);
            zs += __shfl_down_sync(0xFFFFFFFFu, zs, 1, 8);
            if (valid && l == 0) zinv[i] = __fdividef(1.f, (float)NSEQ + zs);
        }
        // ---- vo column sums (threads 192..199: single-slot threads) ----
        if (tid >= 192 && tid < 200) {
            int d8 = tid - 192;
            float s[8];
#pragma unroll
            for (int e = 0; e < 8; e++) s[e] = 0.f;
            for (int j = 0; j < NSEQ; j++) {
                uint4 vv = tvo[buf][j][d8];
                float2 f0 = h2f(vv.x), f1 = h2f(vv.y),
                       f2 = h2f(vv.z), f3 = h2f(vv.w);
                s[0] += f0.x; s[1] += f0.y; s[2] += f1.x; s[3] += f1.y;
                s[4] += f2.x; s[5] += f2.y; s[6] += f3.x; s[7] += f3.y;
            }
#pragma unroll
            for (int e = 0; e < 8; e++) vsumf[d8 * 8 + e] = s[e];
        }
        __syncthreads();
        // ---- output accumulate into registers ----
#pragma unroll
        for (int s2 = 0; s2 < 2; s2++) {
            int slot = tid + s2 * 256;
            if (slot < NSEQ * 8) {
                int i = slot >> 3, d8 = slot & 7;
                float a[8];
#pragma unroll
                for (int e = 0; e < 8; e++) a[e] = vsumf[d8 * 8 + e];
#pragma unroll
                for (int l = 0; l < 8; l++) {
                    float w = wgt[i][l];
                    uint4 vv = tvo[buf][nbr[i][l]][d8];
                    float2 f0 = h2f(vv.x), f1 = h2f(vv.y),
                           f2 = h2f(vv.z), f3 = h2f(vv.w);
                    a[0] += w * f0.x; a[1] += w * f0.y;
                    a[2] += w * f1.x; a[3] += w * f1.y;
                    a[4] += w * f2.x; a[5] += w * f2.y;
                    a[6] += w * f3.x; a[7] += w * f3.y;
                }
                float zi = zinv[i];
#pragma unroll
                for (int e = 0; e < 8; e++) racc[s2][e] += a[e] * zi;
            }
        }
    }

    // ---- final: add bias, write 64-dim rows ----
#pragma unroll
    for (int s2 = 0; s2 < 2; s2++) {
        int slot = tid + s2 * 256;
        if (slot < NSEQ * 8) {
            int i = slot >> 3, d8 = slot & 7;
            float4 o0, o1;
            o0.x = racc[s2][0] + bo[d8 * 8 + 0];
            o0.y = racc[s2][1] + bo[d8 * 8 + 1];
            o0.z = racc[s2][2] + bo[d8 * 8 + 2];
            o0.w = racc[s2][3] + bo[d8 * 8 + 3];
            o1.x = racc[s2][4] + bo[d8 * 8 + 4];
            o1.y = racc[s2][5] + bo[d8 * 8 + 5];
            o1.z = racc[s2][6] + bo[d8 * 8 + 6];
            o1.w = racc[s2][7] + bo[d8 * 8 + 7];
            size_t base = (size_t)b * NSEQ * 64 + (size_t)i * 64 + d8 * 8;
            *reinterpret_cast<float4*>(&out[base])     = o0;
            *reinterpret_cast<float4*>(&out[base + 4]) = o1;
        }
    }
}

// ---------------- launch ----------------
extern "C" void kernel_launch(void* const* d_in, const int* in_sizes, int n_in,
                              void* d_out, int out_size)
{
    const float* queries = (const float*)d_in[0];
    const float* keys    = (const float*)d_in[1];
    const float* values  = (const float*)d_in[2];
    const float* Wq      = (const float*)d_in[3];
    const float* bq      = (const float*)d_in[4];
    const float* Wk      = (const float*)d_in[5];
    const float* bk      = (const float*)d_in[6];
    const float* Wv      = (const float*)d_in[7];
    const float* bv      = (const float*)d_in[8];
    const float* Wo      = (const float*)d_in[9];
    const float* bo      = (const float*)d_in[10];

    float  *bvo;
    __half *qh, *kh, *vh, *qph, *kph, *voh, *wqh, *wkh, *wvoh;
    cudaGetSymbolAddress((void**)&qh,   g_qh);
    cudaGetSymbolAddress((void**)&kh,   g_kh);
    cudaGetSymbolAddress((void**)&vh,   g_vh);
    cudaGetSymbolAddress((void**)&qph,  g_qph);
    cudaGetSymbolAddress((void**)&kph,  g_kph);
    cudaGetSymbolAddress((void**)&voh,  g_voh);
    cudaGetSymbolAddress((void**)&wqh,  g_wqh);
    cudaGetSymbolAddress((void**)&wkh,  g_wkh);
    cudaGetSymbolAddress((void**)&wvoh, g_wvoh);
    cudaGetSymbolAddress((void**)&bvo,  g_bvo);

    cudaFuncSetAttribute(qkv_gemm_h,
                         cudaFuncAttributeMaxDynamicSharedMemorySize, GEMM_SMEM);

    // 1) convert inputs fp32 -> fp16
    conv_inputs<<<(MROWS * DMODEL / 4) / 512, 512>>>(
        (const float4*)queries, (const float4*)keys, (const float4*)values,
        (uint2*)qh, (uint2*)kh, (uint2*)vh);

    // 2) fold Wo into Wv (half), convert Wq/Wk to half
    prep_weights<<<256, 256>>>(Wo, Wv, bv, (const float4*)Wq, (const float4*)Wk,
                               wvoh, bvo, (uint2*)wqh, (uint2*)wkh);

    // 3) projections: q, k, vo all fp16 out (BN=256, 2 CTAs/SM, 0.5 ratio)
    dim3 gridQKV(DMODEL / 256, MTILES, 3);
    qkv_gemm_h<<<gridQKV, 256, GEMM_SMEM>>>(qh, kh, vh, wqh, wkh, wvoh,
                                            bq, bk, bvo, qph, kph, voh);

    // 4) sparse dilated attention + head-summed output, straight to d_out
    dilate_attn<<<BATCH, 256>>>(qph, kph, voh, bo, (float*)d_out);
}

// round 16
// speedup vs baseline: 2.2122x; 2.2122x over previous
#include <cuda_runtime.h>
#include <cuda_fp16.h>
#include <cstdint>
#include <mma.h>
#include <math.h>

using namespace nvcuda;

#define HEADS   8
#define NSEQ    49
#define GRID7   7
#define DMODEL  512
#define BATCH   2048
#define MROWS   (BATCH * NSEQ)   // 100352 = 784 * 128
#define MTILES  (MROWS / 128)    // 784

// ---------------- scratch (no allocations allowed) ----------------
__device__ __half g_qh [(size_t)MROWS * DMODEL];    // half inputs (GEMM A)
__device__ __half g_kh [(size_t)MROWS * DMODEL];
__device__ __half g_vh [(size_t)MROWS * DMODEL];
__device__ __half g_qph[(size_t)MROWS * DMODEL];    // q projection (half)
__device__ __half g_kph[(size_t)MROWS * DMODEL];    // k projection (half)
__device__ __half g_voh[(size_t)MROWS * DMODEL];    // vo projection (half)
__device__ __half g_wqh[DMODEL * DMODEL];
__device__ __half g_wkh[DMODEL * DMODEL];
__device__ __half g_wvoh[DMODEL * DMODEL];
__device__ float  g_bvo[DMODEL];

// ---------------- small helpers ----------------
__device__ __forceinline__ uint32_t h2_bits(__half2 h) {
    union { __half2 h; uint32_t u; } cvt; cvt.h = h; return cvt.u;
}
__device__ __forceinline__ __half2 u2h2(uint32_t u) {
    union { uint32_t u; __half2 h; } cvt; cvt.u = u; return cvt.h;
}
__device__ __forceinline__ uint2 pack4(float x, float y, float z, float w) {
    return make_uint2(h2_bits(__floats2half2_rn(x, y)),
                      h2_bits(__floats2half2_rn(z, w)));
}
__device__ __forceinline__ float2 h2f(uint32_t u) {
    return __half22float2(u2h2(u));
}
// dot of 8 halves: half2 partial chain (4 products), then fp32 reduce
__device__ __forceinline__ float dot8h(uint4 a, uint4 b) {
    __half2 p = __hmul2(u2h2(a.x), u2h2(b.x));
    p = __hfma2(u2h2(a.y), u2h2(b.y), p);
    p = __hfma2(u2h2(a.z), u2h2(b.z), p);
    p = __hfma2(u2h2(a.w), u2h2(b.w), p);
    float2 f = __half22float2(p);
    return f.x + f.y;
}

// ---------------- cp.async helpers ----------------
__device__ __forceinline__ void cp16(void* smem, const void* gmem) {
    uint32_t s = (uint32_t)__cvta_generic_to_shared(smem);
    asm volatile("cp.async.cg.shared.global [%0], [%1], 16;\n" :: "r"(s), "l"(gmem));
}
__device__ __forceinline__ void cp_commit() {
    asm volatile("cp.async.commit_group;\n");
}
template <int N>
__device__ __forceinline__ void cp_wait() {
    asm volatile("cp.async.wait_group %0;\n" :: "n"(N));
}

// =====================================================================
// Input conversion: fp32 -> fp16 for queries/keys/values (one pass).
// =====================================================================
__global__ __launch_bounds__(512)
void conv_inputs(const float4* __restrict__ q, const float4* __restrict__ k,
                 const float4* __restrict__ v,
                 uint2* __restrict__ qh, uint2* __restrict__ kh,
                 uint2* __restrict__ vh)
{
    size_t i = (size_t)blockIdx.x * 512 + threadIdx.x;
    float4 a = q[i];
    float4 b = k[i];
    float4 c = v[i];
    qh[i] = pack4(a.x, a.y, a.z, a.w);
    kh[i] = pack4(b.x, b.y, b.z, b.w);
    vh[i] = pack4(c.x, c.y, c.z, c.w);
}

// =====================================================================
// Weight prep: Wvo = per-head Wo_h @ Wv_h (half), bvo; Wq/Wk -> half.
// =====================================================================
__global__ __launch_bounds__(256)
void prep_weights(const float* __restrict__ Wo, const float* __restrict__ Wv,
                  const float* __restrict__ bv,
                  const float4* __restrict__ Wq, const float4* __restrict__ Wk,
                  __half* __restrict__ wvoh, float* __restrict__ bvo,
                  uint2* __restrict__ wqh, uint2* __restrict__ wkh)
{
    int idx = blockIdx.x * 256 + threadIdx.x;   // 65536 = 512*512/4
    int n = idx >> 7, i4 = idx & 127;
    int h = n >> 6, o = n & 63;
    const float* worow = Wo + (size_t)o * DMODEL + h * 64;
    const float4* wv4  = reinterpret_cast<const float4*>(Wv);
    float4 acc = make_float4(0.f, 0.f, 0.f, 0.f);
#pragma unroll 8
    for (int t = 0; t < 64; t++) {
        float w = worow[t];
        float4 x = wv4[(size_t)(h * 64 + t) * 128 + i4];
        acc.x += w * x.x; acc.y += w * x.y; acc.z += w * x.z; acc.w += w * x.w;
    }
    reinterpret_cast<uint2*>(wvoh)[(size_t)n * 128 + i4] =
        pack4(acc.x, acc.y, acc.z, acc.w);

    float4 a = Wq[idx];
    float4 b = Wk[idx];
    wqh[idx] = pack4(a.x, a.y, a.z, a.w);
    wkh[idx] = pack4(b.x, b.y, b.z, b.w);

    if (idx < DMODEL) {
        int h2 = idx >> 6, o2 = idx & 63;
        float s = 0.f;
        for (int t = 0; t < 64; t++)
            s += Wo[(size_t)o2 * DMODEL + h2 * 64 + t] * bv[h2 * 64 + t];
        bvo[idx] = s;
    }
}

// =====================================================================
// fp16 WMMA GEMM (R14 config — measured best). 3-stage cp.async, BK=64,
// one barrier/chunk, 64x32 warp tiles, BM=BN=128, 256 threads (8 warps,
// 2m x 4n), smem 110.6KB -> 2 CTAs/SM (16 warps/SM, interleaved
// pipelines). acc[4][2]=64 regs fits the 128-reg/2-CTA budget.
// Pipeline order (PROVEN): wait -> sync -> issue -> compute.
//   C[M,512] = A[M,512] @ W[512,512]^T + bias   (all outputs fp16)
// =====================================================================
#define BKH     64
#define BKP     72
#define STAGES  3
#define A_STAGE (128 * BKP * 2)                     // 18432
#define W_STAGE (128 * BKP * 2)                     // 18432
#define GEMM_SMEM (STAGES * (A_STAGE + W_STAGE))    // 110592

__global__ __launch_bounds__(256, 2)
void qkv_gemm_h(const __half* __restrict__ Aq, const __half* __restrict__ Ak,
                const __half* __restrict__ Av,
                const __half* __restrict__ Wqh, const __half* __restrict__ Wkh,
                const __half* __restrict__ Wvoh,
                const float* __restrict__ bq, const float* __restrict__ bk,
                const float* __restrict__ bvo,
                __half* __restrict__ Cq, __half* __restrict__ Ck,
                __half* __restrict__ Cv)
{
    extern __shared__ __align__(16) unsigned char dynsmem[];
    __half (*As)[128][BKP] =
        reinterpret_cast<__half (*)[128][BKP]>(dynsmem);
    __half (*Ws)[128][BKP] =
        reinterpret_cast<__half (*)[128][BKP]>(dynsmem + STAGES * A_STAGE);
    float (*stage)[16][20] = reinterpret_cast<float (*)[16][20]>(dynsmem);

    const int z = blockIdx.z;
    const __half* A    = (z == 0) ? Aq  : (z == 1) ? Ak  : Av;
    const __half* W    = (z == 0) ? Wqh : (z == 1) ? Wkh : Wvoh;
    const float*  bias = (z == 0) ? bq  : (z == 1) ? bk  : bvo;
    __half*       C    = (z == 0) ? Cq  : (z == 1) ? Ck  : Cv;

    const int tid  = threadIdx.x;
    const int warp = tid >> 5;
    const int lane = tid & 31;
    const int wm   = warp >> 2;          // 0..1 -> 64 rows each
    const int wn   = warp & 3;           // 0..3 -> 32 cols each
    const int m0   = blockIdx.y * 128;
    const int n0   = blockIdx.x * 128;

    wmma::fragment<wmma::accumulator, 16, 16, 16, float> acc[4][2];
#pragma unroll
    for (int mf = 0; mf < 4; mf++)
#pragma unroll
        for (int nf = 0; nf < 2; nf++)
            wmma::fill_fragment(acc[mf][nf], 0.0f);

    // per stage: A = 1024 cp16 (4/thread), W = 1024 cp16 (4/thread)
    auto issue_stage = [&](int kc, int s) {
#pragma unroll
        for (int r = 0; r < 4; r++) {
            int idx = tid + r * 256;
            int row = idx >> 3, lc = idx & 7;
            cp16(&As[s][row][lc * 8],
                 A + (size_t)(m0 + row) * DMODEL + kc * BKH + lc * 8);
        }
#pragma unroll
        for (int r = 0; r < 4; r++) {
            int idx = tid + r * 256;
            int row = idx >> 3, lc = idx & 7;
            cp16(&Ws[s][row][lc * 8],
                 W + (size_t)(n0 + row) * DMODEL + kc * BKH + lc * 8);
        }
        cp_commit();
    };

    const int nk = DMODEL / BKH;   // 8
    issue_stage(0, 0);
    issue_stage(1, 1);

    for (int kc = 0; kc < nk; kc++) {
        cp_wait<1>();          // this thread's group kc complete
        __syncthreads();       // ALL threads' group kc visible; buf (kc+2)%3 free
        if (kc + 2 < nk) issue_stage(kc + 2, (kc + 2) % 3);
        else             cp_commit();   // keep group count uniform

        const int buf = kc % 3;
#pragma unroll
        for (int ks = 0; ks < BKH; ks += 16) {
            wmma::fragment<wmma::matrix_b, 16, 16, 16, __half, wmma::col_major> bf[2];
#pragma unroll
            for (int nf = 0; nf < 2; nf++)
                wmma::load_matrix_sync(bf[nf], &Ws[buf][wn * 32 + nf * 16][ks], BKP);
#pragma unroll
            for (int mf = 0; mf < 4; mf++) {
                wmma::fragment<wmma::matrix_a, 16, 16, 16, __half, wmma::row_major> af;
                wmma::load_matrix_sync(af, &As[buf][wm * 64 + mf * 16][ks], BKP);
#pragma unroll
                for (int nf = 0; nf < 2; nf++)
                    wmma::mma_sync(acc[mf][nf], af, bf[nf], acc[mf][nf]);
            }
        }
    }
    __syncthreads();   // all warps done with final tiles before stage alias reuse

    // ---- epilogue: stage fragments, add bias, pack fp16, store 16B ----
#pragma unroll
    for (int mf = 0; mf < 4; mf++)
#pragma unroll
        for (int nf = 0; nf < 2; nf++) {
            wmma::store_matrix_sync(&stage[warp][0][0], acc[mf][nf], 20,
                                    wmma::mem_row_major);
            __syncwarp();
            int r  = lane >> 1;
            int c  = (lane & 1) * 8;
            int gm = m0 + wm * 64 + mf * 16 + r;
            int gn = n0 + wn * 32 + nf * 16 + c;
            float4 v0 = *reinterpret_cast<float4*>(&stage[warp][r][c]);
            float4 v1 = *reinterpret_cast<float4*>(&stage[warp][r][c + 4]);
            float4 b0 = *reinterpret_cast<const float4*>(&bias[gn]);
            float4 b1 = *reinterpret_cast<const float4*>(&bias[gn + 4]);
            uint2 p0 = pack4(v0.x + b0.x, v0.y + b0.y, v0.z + b0.z, v0.w + b0.w);
            uint2 p1 = pack4(v1.x + b1.x, v1.y + b1.y, v1.z + b1.z, v1.w + b1.w);
            *reinterpret_cast<uint4*>(&C[(size_t)gm * DMODEL + gn]) =
                make_uint4(p0.x, p0.y, p1.x, p1.y);
            __syncwarp();
        }
}

// =====================================================================
// Sparse dilated attention (R15 config — measured best, 148us).
// One block per batch, 256 threads, 8 heads sequential; head tiles
// DOUBLE-BUFFERED via cp.async (load h+1 while computing h) ->
// 2 barriers/head, no exposed load latency. HFMA2 partial dots; zinv
// via 8-lane shuffles (full-warp uniform); vo column sums on threads
// 192..199; output partials in registers.
// =====================================================================
__global__ __launch_bounds__(256)
void dilate_attn(const __half* __restrict__ qh, const __half* __restrict__ kh,
                 const __half* __restrict__ voh, const float* __restrict__ bo,
                 float* __restrict__ out)
{
    __shared__ uint4 tq[2][NSEQ][9];   // 64 halves/row (8 used; +1 pad)
    __shared__ uint4 tk[2][NSEQ][9];
    __shared__ uint4 tvo[2][NSEQ][9];
    __shared__ float wgt[NSEQ][8];
    __shared__ float zinv[NSEQ];
    __shared__ float vsumf[64];
    __shared__ int   nbr[NSEQ][8];
    __shared__ int   cnt[NSEQ];

    const int b   = blockIdx.x;
    const int tid = threadIdx.x;
    const size_t bbase = (size_t)b * NSEQ * DMODEL;   // element units
    const uint4* q4 = reinterpret_cast<const uint4*>(qh);
    const uint4* k4 = reinterpret_cast<const uint4*>(kh);
    const uint4* v4 = reinterpret_cast<const uint4*>(voh);

    if (tid < NSEQ) {
        int r = tid / GRID7, c = tid % GRID7;
        int n = 0;
#pragma unroll
        for (int dr = -1; dr <= 1; dr++)
#pragma unroll
            for (int dc = -1; dc <= 1; dc++) {
                if (dr == 0 && dc == 0) continue;
                int rr = r + dr, cc = c + dc;
                if (rr >= 0 && rr < GRID7 && cc >= 0 && cc < GRID7)
                    nbr[tid][n++] = rr * GRID7 + cc;
            }
        cnt[tid] = n;
        for (int l = n; l < 8; l++) nbr[tid][l] = 0;
    }

    auto issue_head = [&](int h, int buf) {
        size_t base8 = (bbase + h * 64) / 8;   // uint4 units
#pragma unroll
        for (int s2 = 0; s2 < 2; s2++) {
            int e = tid + s2 * 256;
            if (e < NSEQ * 8) {
                int n = e >> 3, d8 = e & 7;
                size_t g = base8 + (size_t)n * 64 + d8;
                cp16(&tq[buf][n][d8],  q4 + g);
                cp16(&tk[buf][n][d8],  k4 + g);
                cp16(&tvo[buf][n][d8], v4 + g);
            }
        }
        cp_commit();
    };

    // register output accumulators: slot = tid + s2*256 -> (i = slot/8, d8 = slot%8)
    float racc[2][8];
#pragma unroll
    for (int s2 = 0; s2 < 2; s2++)
#pragma unroll
        for (int e = 0; e < 8; e++) racc[s2][e] = 0.f;

    issue_head(0, 0);

    for (int h = 0; h < HEADS; h++) {
        const int buf = h & 1;
        cp_wait<0>();       // only group h outstanding here
        __syncthreads();    // tiles h visible; output(h-1) done (wgt/buf reuse safe)
        if (h + 1 < HEADS) issue_head(h + 1, buf ^ 1);

        // ---- sparse QK dots + per-row zinv (uniform full-warp shuffles) ----
#pragma unroll
        for (int s2 = 0; s2 < 2; s2++) {
            int slot = tid + s2 * 256;
            bool valid = slot < NSEQ * 8;
            int i = valid ? (slot >> 3) : 0;
            int l = slot & 7;
            float w = 0.f;
            if (valid && l < cnt[i]) {
                int j = nbr[i][l];
                float dot = 0.f;
#pragma unroll
                for (int d8 = 0; d8 < 8; d8++)
                    dot += dot8h(tq[buf][i][d8], tk[buf][j][d8]);
                w = __expf(dot * 0.125f) - 1.f;
            }
            if (valid) wgt[i][l] = w;
            float zs = w;   // all 32 lanes participate; invalid lanes carry 0
            zs += __shfl_down_sync(0xFFFFFFFFu, zs, 4, 8);
            zs += __shfl_down_sync(0xFFFFFFFFu, zs, 2, 8);
            zs += __shfl_down_sync(0xFFFFFFFFu, zs, 1, 8);
            if (valid && l == 0) zinv[i] = __fdividef(1.f, (float)NSEQ + zs);
        }
        // ---- vo column sums (threads 192..199: single-slot threads) ----
        if (tid >= 192 && tid < 200) {
            int d8 = tid - 192;
            float s[8];
#pragma unroll
            for (int e = 0; e < 8; e++) s[e] = 0.f;
            for (int j = 0; j < NSEQ; j++) {
                uint4 vv = tvo[buf][j][d8];
                float2 f0 = h2f(vv.x), f1 = h2f(vv.y),
                       f2 = h2f(vv.z), f3 = h2f(vv.w);
                s[0] += f0.x; s[1] += f0.y; s[2] += f1.x; s[3] += f1.y;
                s[4] += f2.x; s[5] += f2.y; s[6] += f3.x; s[7] += f3.y;
            }
#pragma unroll
            for (int e = 0; e < 8; e++) vsumf[d8 * 8 + e] = s[e];
        }
        __syncthreads();
        // ---- output accumulate into registers ----
#pragma unroll
        for (int s2 = 0; s2 < 2; s2++) {
            int slot = tid + s2 * 256;
            if (slot < NSEQ * 8) {
                int i = slot >> 3, d8 = slot & 7;
                float a[8];
#pragma unroll
                for (int e = 0; e < 8; e++) a[e] = vsumf[d8 * 8 + e];
#pragma unroll
                for (int l = 0; l < 8; l++) {
                    float w = wgt[i][l];
                    uint4 vv = tvo[buf][nbr[i][l]][d8];
                    float2 f0 = h2f(vv.x), f1 = h2f(vv.y),
                           f2 = h2f(vv.z), f3 = h2f(vv.w);
                    a[0] += w * f0.x; a[1] += w * f0.y;
                    a[2] += w * f1.x; a[3] += w * f1.y;
                    a[4] += w * f2.x; a[5] += w * f2.y;
                    a[6] += w * f3.x; a[7] += w * f3.y;
                }
                float zi = zinv[i];
#pragma unroll
                for (int e = 0; e < 8; e++) racc[s2][e] += a[e] * zi;
            }
        }
    }

    // ---- final: add bias, write 64-dim rows ----
#pragma unroll
    for (int s2 = 0; s2 < 2; s2++) {
        int slot = tid + s2 * 256;
        if (slot < NSEQ * 8) {
            int i = slot >> 3, d8 = slot & 7;
            float4 o0, o1;
            o0.x = racc[s2][0] + bo[d8 * 8 + 0];
            o0.y = racc[s2][1] + bo[d8 * 8 + 1];
            o0.z = racc[s2][2] + bo[d8 * 8 + 2];
            o0.w = racc[s2][3] + bo[d8 * 8 + 3];
            o1.x = racc[s2][4] + bo[d8 * 8 + 4];
            o1.y = racc[s2][5] + bo[d8 * 8 + 5];
            o1.z = racc[s2][6] + bo[d8 * 8 + 6];
            o1.w = racc[s2][7] + bo[d8 * 8 + 7];
            size_t base = (size_t)b * NSEQ * 64 + (size_t)i * 64 + d8 * 8;
            *reinterpret_cast<float4*>(&out[base])     = o0;
            *reinterpret_cast<float4*>(&out[base + 4]) = o1;
        }
    }
}

// ---------------- launch ----------------
extern "C" void kernel_launch(void* const* d_in, const int* in_sizes, int n_in,
                              void* d_out, int out_size)
{
    const float* queries = (const float*)d_in[0];
    const float* keys    = (const float*)d_in[1];
    const float* values  = (const float*)d_in[2];
    const float* Wq      = (const float*)d_in[3];
    const float* bq      = (const float*)d_in[4];
    const float* Wk      = (const float*)d_in[5];
    const float* bk      = (const float*)d_in[6];
    const float* Wv      = (const float*)d_in[7];
    const float* bv      = (const float*)d_in[8];
    const float* Wo      = (const float*)d_in[9];
    const float* bo      = (const float*)d_in[10];

    float  *bvo;
    __half *qh, *kh, *vh, *qph, *kph, *voh, *wqh, *wkh, *wvoh;
    cudaGetSymbolAddress((void**)&qh,   g_qh);
    cudaGetSymbolAddress((void**)&kh,   g_kh);
    cudaGetSymbolAddress((void**)&vh,   g_vh);
    cudaGetSymbolAddress((void**)&qph,  g_qph);
    cudaGetSymbolAddress((void**)&kph,  g_kph);
    cudaGetSymbolAddress((void**)&voh,  g_voh);
    cudaGetSymbolAddress((void**)&wqh,  g_wqh);
    cudaGetSymbolAddress((void**)&wkh,  g_wkh);
    cudaGetSymbolAddress((void**)&wvoh, g_wvoh);
    cudaGetSymbolAddress((void**)&bvo,  g_bvo);

    cudaFuncSetAttribute(qkv_gemm_h,
                         cudaFuncAttributeMaxDynamicSharedMemorySize, GEMM_SMEM);

    // 1) convert inputs fp32 -> fp16
    conv_inputs<<<(MROWS * DMODEL / 4) / 512, 512>>>(
        (const float4*)queries, (const float4*)keys, (const float4*)values,
        (uint2*)qh, (uint2*)kh, (uint2*)vh);

    // 2) fold Wo into Wv (half), convert Wq/Wk to half
    prep_weights<<<256, 256>>>(Wo, Wv, bv, (const float4*)Wq, (const float4*)Wk,
                               wvoh, bvo, (uint2*)wqh, (uint2*)wkh);

    // 3) projections: q, k, vo all fp16 out (R14 GEMM: 2 CTAs/SM)
    dim3 gridQKV(DMODEL / 128, MTILES, 3);
    qkv_gemm_h<<<gridQKV, 256, GEMM_SMEM>>>(qh, kh, vh, wqh, wkh, wvoh,
                                            bq, bk, bvo, qph, kph, voh);

    // 4) sparse dilated attention + head-summed output, straight to d_out
    dilate_attn<<<BATCH, 256>>>(qph, kph, voh, bo, (float*)d_out);
}